// round 4
// baseline (speedup 1.0000x reference)
#include <cuda_runtime.h>
#include <cstdint>

#define NN 100000
#define NE 1600000
#define DIN 128

// ---------------- scratch (static __device__, no allocation) ----------------
__device__ __align__(16) float g_deg[NN];       // degree -> deg_inv_sqrt (in place)
__device__ int   g_cnt[NN];                     // in-degree counts (edges only)
__device__ int   g_cur[NN];                     // bucket cursors
__device__ int   g_rowstart[NN + 1];            // CSR row offsets (by dst)
__device__ int   g_esrc[NE];                    // CSR-sorted src
__device__ __align__(16) float g_enorm[NE];     // CSR-sorted edge norm
__device__ __align__(16) float g_h[(size_t)NN * 128];   // transformed features
__device__ __align__(16) float g_a[(size_t)NN * 128];   // activation ping
__device__ __align__(16) float g_b[(size_t)NN * 128];   // activation pong

// buffer selector: kernels address scratch directly (no cudaGetSymbolAddress)
template <int SEL>
__device__ __forceinline__ float* buf() {
    if constexpr (SEL == 0) return g_h;
    else if constexpr (SEL == 1) return g_a;
    else return g_b;
}

// ---------------- preamble ----------------
__global__ void k_init() {
    int i = blockIdx.x * blockDim.x + threadIdx.x;
    if (i < NN) { g_deg[i] = 1.0f; g_cnt[i] = 0; g_cur[i] = 0; }
}

// edge_index delivered as int32: [0..NE) = src, [NE..2NE) = dst
__global__ void k_deg_acc(const int* __restrict__ ei,
                          const float* __restrict__ w) {
    int e = blockIdx.x * blockDim.x + threadIdx.x;
    if (e >= NE) return;
    int d = ei[NE + e];
    atomicAdd(&g_deg[d], w[e]);
    atomicAdd(&g_cnt[d], 1);
}

__global__ void k_dinv() {
    int i = blockIdx.x * blockDim.x + threadIdx.x;
    if (i < NN) g_deg[i] = rsqrtf(g_deg[i]);   // deg >= 1 (self-loop)
}

// single-block exclusive scan of g_cnt -> g_rowstart  (1024 threads)
__global__ void k_scan() {
    __shared__ int part[1024];
    const int T = 1024;
    const int chunk = (NN + T - 1) / T;
    int t = threadIdx.x;
    int lo = t * chunk;
    int hi = min(lo + chunk, NN);
    int s = 0;
    for (int i = lo; i < hi; i++) s += g_cnt[i];
    part[t] = s;
    __syncthreads();
    for (int off = 1; off < T; off <<= 1) {
        int v = (t >= off) ? part[t - off] : 0;
        __syncthreads();
        part[t] += v;
        __syncthreads();
    }
    int run = (t == 0) ? 0 : part[t - 1];
    for (int i = lo; i < hi; i++) {
        g_rowstart[i] = run;
        run += g_cnt[i];
    }
    if (lo < NN && hi == NN) g_rowstart[NN] = run;
}

// bucket edges by dst; compute per-edge norm into sorted slot
__global__ void k_bucket(const int* __restrict__ ei,
                         const float* __restrict__ w) {
    int e = blockIdx.x * blockDim.x + threadIdx.x;
    if (e >= NE) return;
    int s = ei[e];
    int d = ei[NE + e];
    int pos = g_rowstart[d] + atomicAdd(&g_cur[d], 1);
    g_esrc[pos]  = s;
    g_enorm[pos] = g_deg[s] * w[e] * g_deg[d];
}

// ---------------- SGEMM: g_h = X @ W ----------------
// block = 256 threads, BM=64 rows, BK=32, thread tile TM=4 x TN=DOUT/16
// XSEL: -1 -> use Xext argument; else buf<XSEL>()
template <int DOUT, int XSEL>
__global__ void k_gemm(const float* __restrict__ Xext,
                       const float* __restrict__ W) {
    constexpr int BM = 64, BK = 32, TM = 4, TN = DOUT / 16;
    __shared__ float Xs[BK][BM];
    __shared__ float Ws[BK][DOUT];

    const float* X = (XSEL < 0) ? Xext : buf<(XSEL < 0) ? 0 : XSEL>();
    float* H = g_h;

    const int tid  = threadIdx.x;
    const int row0 = blockIdx.x * BM;
    const int tr   = tid >> 4;
    const int tc   = tid & 15;

    float acc[TM][TN];
#pragma unroll
    for (int a = 0; a < TM; a++)
#pragma unroll
        for (int b = 0; b < TN; b++) acc[a][b] = 0.f;

    for (int k0 = 0; k0 < DIN; k0 += BK) {
#pragma unroll
        for (int i = tid; i < BM * BK; i += 256) {
            int m = i / BK, k = i % BK;
            int r = row0 + m;
            Xs[k][m] = (r < NN) ? X[(size_t)r * DIN + k0 + k] : 0.f;
        }
#pragma unroll
        for (int i = tid; i < BK * DOUT; i += 256) {
            int k = i / DOUT, c = i % DOUT;
            Ws[k][c] = W[(size_t)(k0 + k) * DOUT + c];
        }
        __syncthreads();
#pragma unroll
        for (int k = 0; k < BK; k++) {
            float xv[TM];
#pragma unroll
            for (int a = 0; a < TM; a++) xv[a] = Xs[k][tr * TM + a];
            float wv[TN];
#pragma unroll
            for (int b = 0; b < TN; b++) wv[b] = Ws[k][tc * TN + b];
#pragma unroll
            for (int a = 0; a < TM; a++)
#pragma unroll
                for (int b = 0; b < TN; b++) acc[a][b] += xv[a] * wv[b];
        }
        __syncthreads();
    }

#pragma unroll
    for (int a = 0; a < TM; a++) {
        int r = row0 + tr * TM + a;
        if (r >= NN) continue;
#pragma unroll
        for (int b = 0; b < TN; b++)
            H[(size_t)r * DOUT + tc * TN + b] = acc[a][b];
    }
}

// ------- fused aggregate: OUT[n] = sum_{CSR[n]} norm*g_h[src] + dinv^2*g_h[n] + bias, relu ----
// one warp per node; DOUT=128 -> float4/lane, DOUT=64 -> float2/lane
// OSEL: -1 -> write OUText argument; else buf<OSEL>()
template <int DOUT, bool RELU, int OSEL>
__global__ void k_agg(const float* __restrict__ bias,
                      float* __restrict__ OUText) {
    int warp = (blockIdx.x * blockDim.x + threadIdx.x) >> 5;
    int lane = threadIdx.x & 31;
    if (warp >= NN) return;

    float* OUT = (OSEL < 0) ? OUText : buf<(OSEL < 0) ? 0 : OSEL>();
    const float* H = g_h;

    int beg = g_rowstart[warp];
    int end = g_rowstart[warp + 1];
    float din = g_deg[warp];
    float sn  = din * din;

    if (DOUT == 128) {
        const float4* H4 = reinterpret_cast<const float4*>(H);
        float4 h = H4[(size_t)warp * 32 + lane];
        float4 acc = make_float4(h.x * sn, h.y * sn, h.z * sn, h.w * sn);
        for (int e = beg; e < end; e++) {
            int   s = g_esrc[e];
            float w = g_enorm[e];
            float4 v = H4[(size_t)s * 32 + lane];
            acc.x += w * v.x; acc.y += w * v.y;
            acc.z += w * v.z; acc.w += w * v.w;
        }
        float4 bb = reinterpret_cast<const float4*>(bias)[lane];
        acc.x += bb.x; acc.y += bb.y; acc.z += bb.z; acc.w += bb.w;
        if (RELU) {
            acc.x = fmaxf(acc.x, 0.f); acc.y = fmaxf(acc.y, 0.f);
            acc.z = fmaxf(acc.z, 0.f); acc.w = fmaxf(acc.w, 0.f);
        }
        reinterpret_cast<float4*>(OUT)[(size_t)warp * 32 + lane] = acc;
    } else {
        const float2* H2 = reinterpret_cast<const float2*>(H);
        float2 h = H2[(size_t)warp * 32 + lane];
        float2 acc = make_float2(h.x * sn, h.y * sn);
        for (int e = beg; e < end; e++) {
            int   s = g_esrc[e];
            float w = g_enorm[e];
            float2 v = H2[(size_t)s * 32 + lane];
            acc.x += w * v.x; acc.y += w * v.y;
        }
        float2 bb = reinterpret_cast<const float2*>(bias)[lane];
        acc.x += bb.x; acc.y += bb.y;
        if (RELU) { acc.x = fmaxf(acc.x, 0.f); acc.y = fmaxf(acc.y, 0.f); }
        reinterpret_cast<float2*>(OUT)[(size_t)warp * 32 + lane] = acc;
    }
}

// ---------------- driver (no runtime API calls besides launches) ----------------
extern "C" void kernel_launch(void* const* d_in, const int* in_sizes, int n_in,
                              void* d_out, int out_size) {
    const float* x  = (const float*)d_in[0];
    const int*   ei = (const int*)d_in[1];      // int64 in reference -> int32 per harness
    const float* ew = (const float*)d_in[2];
    const float* W0 = (const float*)d_in[3];
    const float* b0 = (const float*)d_in[4];
    const float* W1 = (const float*)d_in[5];
    const float* b1 = (const float*)d_in[6];
    const float* W2 = (const float*)d_in[7];
    const float* b2 = (const float*)d_in[8];
    float*       out = (float*)d_out;

    const int T = 256;
    // CSR + normalization preamble
    k_init<<<(NN + T - 1) / T, T>>>();
    k_deg_acc<<<(NE + T - 1) / T, T>>>(ei, ew);
    k_dinv<<<(NN + T - 1) / T, T>>>();
    k_scan<<<1, 1024>>>();
    k_bucket<<<(NE + T - 1) / T, T>>>(ei, ew);

    const int gemm_blocks = (NN + 63) / 64;
    const int agg_blocks  = (NN * 32 + T - 1) / T;   // one warp per node

    // layer 0: x -> g_a (d=128, relu)
    k_gemm<128, -1><<<gemm_blocks, 256>>>(x, W0);
    k_agg<128, true, 1><<<agg_blocks, T>>>(b0, nullptr);

    // layer 1: g_a -> g_b (d=128, relu)
    k_gemm<128, 1><<<gemm_blocks, 256>>>(nullptr, W1);
    k_agg<128, true, 2><<<agg_blocks, T>>>(b1, nullptr);

    // layer 2: g_b -> out (d=64, no relu)
    k_gemm<64, 2><<<gemm_blocks, 256>>>(nullptr, W2);
    k_agg<64, false, -1><<<agg_blocks, T>>>(b2, out);
}

// round 5
// speedup vs baseline: 1.1510x; 1.1510x over previous
#include <cuda_runtime.h>
#include <cstdint>

#define NN 100000
#define NE 1600000
#define DIN 128

#define CHUNK 1024
#define NBLK ((NN + CHUNK - 1) / CHUNK)   // 98 scan blocks

// ---------------- scratch (static __device__, no allocation) ----------------
__device__ __align__(16) float g_deg[NN];       // degree -> deg_inv_sqrt (in place)
__device__ int   g_cnt[NN];                     // in-degree counts (edges only)
__device__ int   g_cur[NN];                     // bucket cursors
__device__ int   g_rowstart[NN + 1];            // CSR row offsets (by dst)
__device__ int   g_bsum[NBLK];                  // per-chunk edge-count sums
__device__ int   g_bpre[NBLK];                  // exclusive prefix of chunk sums
__device__ int   g_esrc[NE];                    // CSR-sorted src
__device__ __align__(16) float g_enorm[NE];     // CSR-sorted edge norm
__device__ __align__(16) float g_h[(size_t)NN * 128];   // transformed features
__device__ __align__(16) float g_a[(size_t)NN * 128];   // activation ping
__device__ __align__(16) float g_b[(size_t)NN * 128];   // activation pong

template <int SEL>
__device__ __forceinline__ float* buf() {
    if constexpr (SEL == 0) return g_h;
    else if constexpr (SEL == 1) return g_a;
    else return g_b;
}

// ---------------- preamble ----------------
__global__ void k_init() {
    int i = blockIdx.x * blockDim.x + threadIdx.x;
    if (i < NN) { g_deg[i] = 1.0f; g_cnt[i] = 0; g_cur[i] = 0; }
}

// edge_index delivered as int32: [0..NE) = src, [NE..2NE) = dst
__global__ void k_deg_acc(const int* __restrict__ ei,
                          const float* __restrict__ w) {
    int e = blockIdx.x * blockDim.x + threadIdx.x;
    if (e >= NE) return;
    int d = ei[NE + e];
    atomicAdd(&g_deg[d], w[e]);
    atomicAdd(&g_cnt[d], 1);
}

// scan phase A: per-chunk sums of g_cnt; also finalize deg_inv_sqrt
__global__ void k_scan_a() {
    __shared__ int red[256];
    int b = blockIdx.x, t = threadIdx.x;
    int base = b * CHUNK;
    int s = 0;
#pragma unroll
    for (int j = 0; j < CHUNK / 256; j++) {
        int i = base + j * 256 + t;
        if (i < NN) {
            s += g_cnt[i];
            g_deg[i] = rsqrtf(g_deg[i]);   // deg >= 1 (self-loop), fused here
        }
    }
    red[t] = s;
    __syncthreads();
    for (int off = 128; off > 0; off >>= 1) {
        if (t < off) red[t] += red[t + off];
        __syncthreads();
    }
    if (t == 0) g_bsum[b] = red[0];
}

// scan phase B: exclusive scan of NBLK chunk sums (1 block, 128 threads)
__global__ void k_scan_b() {
    __shared__ int sh[128];
    int t = threadIdx.x;
    sh[t] = (t < NBLK) ? g_bsum[t] : 0;
    __syncthreads();
    for (int off = 1; off < 128; off <<= 1) {
        int v = (t >= off) ? sh[t - off] : 0;
        __syncthreads();
        sh[t] += v;
        __syncthreads();
    }
    if (t < NBLK) g_bpre[t] = (t == 0) ? 0 : sh[t - 1];
    if (t == NBLK - 1) g_rowstart[NN] = sh[t];   // total edge count = NE
}

// scan phase C: local exclusive scan within chunk + chunk prefix
__global__ void k_scan_c() {
    __shared__ int sh[256];
    int b = blockIdx.x, t = threadIdx.x;
    int base = b * CHUNK;
    constexpr int PT = CHUNK / 256;   // 4 nodes per thread
    int c[PT];
    int s = 0;
#pragma unroll
    for (int j = 0; j < PT; j++) {
        int i = base + t * PT + j;
        c[j] = (i < NN) ? g_cnt[i] : 0;
        s += c[j];
    }
    sh[t] = s;
    __syncthreads();
    for (int off = 1; off < 256; off <<= 1) {
        int v = (t >= off) ? sh[t - off] : 0;
        __syncthreads();
        sh[t] += v;
        __syncthreads();
    }
    int run = g_bpre[b] + ((t == 0) ? 0 : sh[t - 1]);
#pragma unroll
    for (int j = 0; j < PT; j++) {
        int i = base + t * PT + j;
        if (i < NN) g_rowstart[i] = run;
        run += c[j];
    }
}

// bucket edges by dst; compute per-edge norm into sorted slot
__global__ void k_bucket(const int* __restrict__ ei,
                         const float* __restrict__ w) {
    int e = blockIdx.x * blockDim.x + threadIdx.x;
    if (e >= NE) return;
    int s = ei[e];
    int d = ei[NE + e];
    int pos = g_rowstart[d] + atomicAdd(&g_cur[d], 1);
    g_esrc[pos]  = s;
    g_enorm[pos] = g_deg[s] * w[e] * g_deg[d];
}

// ---------------- SGEMM: g_h = X @ W ----------------
template <int DOUT, int XSEL>
__global__ void k_gemm(const float* __restrict__ Xext,
                       const float* __restrict__ W) {
    constexpr int BM = 64, BK = 32, TM = 4, TN = DOUT / 16;
    __shared__ float Xs[BK][BM];
    __shared__ float Ws[BK][DOUT];

    const float* X = (XSEL < 0) ? Xext : buf<(XSEL < 0) ? 0 : XSEL>();
    float* H = g_h;

    const int tid  = threadIdx.x;
    const int row0 = blockIdx.x * BM;
    const int tr   = tid >> 4;
    const int tc   = tid & 15;

    float acc[TM][TN];
#pragma unroll
    for (int a = 0; a < TM; a++)
#pragma unroll
        for (int b = 0; b < TN; b++) acc[a][b] = 0.f;

    for (int k0 = 0; k0 < DIN; k0 += BK) {
        // X tile: 64x32 floats, scalar coalesced
#pragma unroll
        for (int i = tid; i < BM * BK; i += 256) {
            int m = i / BK, k = i % BK;
            int r = row0 + m;
            Xs[k][m] = (r < NN) ? X[(size_t)r * DIN + k0 + k] : 0.f;
        }
        // W tile: 32xDOUT floats, float4 vectorized
#pragma unroll
        for (int i4 = tid; i4 < BK * DOUT / 4; i4 += 256) {
            int k = i4 / (DOUT / 4), c4 = i4 % (DOUT / 4);
            float4 wv4 = reinterpret_cast<const float4*>(
                &W[(size_t)(k0 + k) * DOUT])[c4];
            *reinterpret_cast<float4*>(&Ws[k][c4 * 4]) = wv4;
        }
        __syncthreads();
#pragma unroll
        for (int k = 0; k < BK; k++) {
            float xv[TM];
#pragma unroll
            for (int a = 0; a < TM; a++) xv[a] = Xs[k][tr * TM + a];
            float wv[TN];
#pragma unroll
            for (int b = 0; b < TN; b++) wv[b] = Ws[k][tc * TN + b];
#pragma unroll
            for (int a = 0; a < TM; a++)
#pragma unroll
                for (int b = 0; b < TN; b++) acc[a][b] += xv[a] * wv[b];
        }
        __syncthreads();
    }

#pragma unroll
    for (int a = 0; a < TM; a++) {
        int r = row0 + tr * TM + a;
        if (r >= NN) continue;
#pragma unroll
        for (int b = 0; b < TN; b++)
            H[(size_t)r * DOUT + tc * TN + b] = acc[a][b];
    }
}

// ------- fused aggregate: OUT[n] = sum_{CSR[n]} norm*g_h[src] + dinv^2*g_h[n] + bias, relu ----
template <int DOUT, bool RELU, int OSEL>
__global__ void k_agg(const float* __restrict__ bias,
                      float* __restrict__ OUText) {
    int warp = (blockIdx.x * blockDim.x + threadIdx.x) >> 5;
    int lane = threadIdx.x & 31;
    if (warp >= NN) return;

    float* OUT = (OSEL < 0) ? OUText : buf<(OSEL < 0) ? 0 : OSEL>();
    const float* H = g_h;

    int beg = g_rowstart[warp];
    int end = g_rowstart[warp + 1];
    float din = g_deg[warp];
    float sn  = din * din;

    if (DOUT == 128) {
        const float4* H4 = reinterpret_cast<const float4*>(H);
        float4 h = H4[(size_t)warp * 32 + lane];
        float4 acc = make_float4(h.x * sn, h.y * sn, h.z * sn, h.w * sn);
        for (int e = beg; e < end; e++) {
            int   s = g_esrc[e];
            float w = g_enorm[e];
            float4 v = H4[(size_t)s * 32 + lane];
            acc.x += w * v.x; acc.y += w * v.y;
            acc.z += w * v.z; acc.w += w * v.w;
        }
        float4 bb = reinterpret_cast<const float4*>(bias)[lane];
        acc.x += bb.x; acc.y += bb.y; acc.z += bb.z; acc.w += bb.w;
        if (RELU) {
            acc.x = fmaxf(acc.x, 0.f); acc.y = fmaxf(acc.y, 0.f);
            acc.z = fmaxf(acc.z, 0.f); acc.w = fmaxf(acc.w, 0.f);
        }
        reinterpret_cast<float4*>(OUT)[(size_t)warp * 32 + lane] = acc;
    } else {
        const float2* H2 = reinterpret_cast<const float2*>(H);
        float2 h = H2[(size_t)warp * 32 + lane];
        float2 acc = make_float2(h.x * sn, h.y * sn);
        for (int e = beg; e < end; e++) {
            int   s = g_esrc[e];
            float w = g_enorm[e];
            float2 v = H2[(size_t)s * 32 + lane];
            acc.x += w * v.x; acc.y += w * v.y;
        }
        float2 bb = reinterpret_cast<const float2*>(bias)[lane];
        acc.x += bb.x; acc.y += bb.y;
        if (RELU) { acc.x = fmaxf(acc.x, 0.f); acc.y = fmaxf(acc.y, 0.f); }
        reinterpret_cast<float2*>(OUT)[(size_t)warp * 32 + lane] = acc;
    }
}

// ---------------- driver (launches only) ----------------
extern "C" void kernel_launch(void* const* d_in, const int* in_sizes, int n_in,
                              void* d_out, int out_size) {
    const float* x  = (const float*)d_in[0];
    const int*   ei = (const int*)d_in[1];
    const float* ew = (const float*)d_in[2];
    const float* W0 = (const float*)d_in[3];
    const float* b0 = (const float*)d_in[4];
    const float* W1 = (const float*)d_in[5];
    const float* b1 = (const float*)d_in[6];
    const float* W2 = (const float*)d_in[7];
    const float* b2 = (const float*)d_in[8];
    float*       out = (float*)d_out;

    const int T = 256;
    // CSR + normalization preamble
    k_init<<<(NN + T - 1) / T, T>>>();
    k_deg_acc<<<(NE + T - 1) / T, T>>>(ei, ew);
    k_scan_a<<<NBLK, 256>>>();
    k_scan_b<<<1, 128>>>();
    k_scan_c<<<NBLK, 256>>>();
    k_bucket<<<(NE + T - 1) / T, T>>>(ei, ew);

    const int gemm_blocks = (NN + 63) / 64;
    const int agg_blocks  = (NN * 32 + T - 1) / T;

    // layer 0: x -> g_a (d=128, relu)
    k_gemm<128, -1><<<gemm_blocks, 256>>>(x, W0);
    k_agg<128, true, 1><<<agg_blocks, T>>>(b0, nullptr);

    // layer 1: g_a -> g_b (d=128, relu)
    k_gemm<128, 1><<<gemm_blocks, 256>>>(nullptr, W1);
    k_agg<128, true, 2><<<agg_blocks, T>>>(b1, nullptr);

    // layer 2: g_b -> out (d=64, no relu)
    k_gemm<64, 2><<<gemm_blocks, 256>>>(nullptr, W2);
    k_agg<64, false, -1><<<agg_blocks, T>>>(b2, out);
}

// round 6
// speedup vs baseline: 1.7674x; 1.5356x over previous
#include <cuda_runtime.h>
#include <cstdint>

#define NN 100000
#define NE 1600000
#define DIN 128

#define CHUNK 1024
#define NBLK ((NN + CHUNK - 1) / CHUNK)   // 98 scan blocks

// ---------------- scratch (static __device__, no allocation) ----------------
__device__ __align__(16) float g_deg[NN];       // degree -> deg_inv_sqrt (in place)
__device__ int   g_cnt[NN];                     // in-degree counts (edges only)
__device__ int   g_cur[NN];                     // bucket cursors
__device__ int   g_rowstart[NN + 1];            // CSR row offsets (by dst)
__device__ int   g_bsum[NBLK];                  // per-chunk edge-count sums
__device__ int   g_bpre[NBLK];                  // exclusive prefix of chunk sums
__device__ int   g_esrc[NE];                    // CSR-sorted src
__device__ __align__(16) float g_enorm[NE];     // CSR-sorted edge norm
__device__ __align__(16) float g_h[(size_t)NN * 128];   // transformed features
__device__ __align__(16) float g_a[(size_t)NN * 128];   // activation ping
__device__ __align__(16) float g_b[(size_t)NN * 128];   // activation pong

template <int SEL>
__device__ __forceinline__ float* buf() {
    if constexpr (SEL == 0) return g_h;
    else if constexpr (SEL == 1) return g_a;
    else return g_b;
}

// ---------------- packed f32x2 helpers ----------------
__device__ __forceinline__ uint64_t pack2(float lo, float hi) {
    uint64_t r;
    asm("mov.b64 %0, {%1, %2};" : "=l"(r) : "f"(lo), "f"(hi));
    return r;
}
__device__ __forceinline__ void ffma2(uint64_t& d, uint64_t a, uint64_t b) {
    asm("fma.rn.f32x2 %0, %1, %2, %0;" : "+l"(d) : "l"(a), "l"(b));
}
__device__ __forceinline__ void unpack2(uint64_t v, float& lo, float& hi) {
    asm("mov.b64 {%0, %1}, %2;" : "=f"(lo), "=f"(hi) : "l"(v));
}

// ---------------- preamble ----------------
__global__ void k_init() {
    int i = blockIdx.x * blockDim.x + threadIdx.x;
    if (i < NN) { g_deg[i] = 1.0f; g_cnt[i] = 0; g_cur[i] = 0; }
}

// edge_index delivered as int32: [0..NE) = src, [NE..2NE) = dst
__global__ void k_deg_acc(const int* __restrict__ ei,
                          const float* __restrict__ w) {
    int e = blockIdx.x * blockDim.x + threadIdx.x;
    if (e >= NE) return;
    int d = ei[NE + e];
    atomicAdd(&g_deg[d], w[e]);
    atomicAdd(&g_cnt[d], 1);
}

// scan phase A: per-chunk sums of g_cnt; also finalize deg_inv_sqrt
__global__ void k_scan_a() {
    __shared__ int red[256];
    int b = blockIdx.x, t = threadIdx.x;
    int base = b * CHUNK;
    int s = 0;
#pragma unroll
    for (int j = 0; j < CHUNK / 256; j++) {
        int i = base + j * 256 + t;
        if (i < NN) {
            s += g_cnt[i];
            g_deg[i] = rsqrtf(g_deg[i]);
        }
    }
    red[t] = s;
    __syncthreads();
    for (int off = 128; off > 0; off >>= 1) {
        if (t < off) red[t] += red[t + off];
        __syncthreads();
    }
    if (t == 0) g_bsum[b] = red[0];
}

// scan phase B: exclusive scan of NBLK chunk sums
__global__ void k_scan_b() {
    __shared__ int sh[128];
    int t = threadIdx.x;
    sh[t] = (t < NBLK) ? g_bsum[t] : 0;
    __syncthreads();
    for (int off = 1; off < 128; off <<= 1) {
        int v = (t >= off) ? sh[t - off] : 0;
        __syncthreads();
        sh[t] += v;
        __syncthreads();
    }
    if (t < NBLK) g_bpre[t] = (t == 0) ? 0 : sh[t - 1];
    if (t == NBLK - 1) g_rowstart[NN] = sh[t];
}

// scan phase C: local exclusive scan within chunk + chunk prefix
__global__ void k_scan_c() {
    __shared__ int sh[256];
    int b = blockIdx.x, t = threadIdx.x;
    int base = b * CHUNK;
    constexpr int PT = CHUNK / 256;
    int c[PT];
    int s = 0;
#pragma unroll
    for (int j = 0; j < PT; j++) {
        int i = base + t * PT + j;
        c[j] = (i < NN) ? g_cnt[i] : 0;
        s += c[j];
    }
    sh[t] = s;
    __syncthreads();
    for (int off = 1; off < 256; off <<= 1) {
        int v = (t >= off) ? sh[t - off] : 0;
        __syncthreads();
        sh[t] += v;
        __syncthreads();
    }
    int run = g_bpre[b] + ((t == 0) ? 0 : sh[t - 1]);
#pragma unroll
    for (int j = 0; j < PT; j++) {
        int i = base + t * PT + j;
        if (i < NN) g_rowstart[i] = run;
        run += c[j];
    }
}

// bucket edges by dst; compute per-edge norm into sorted slot
__global__ void k_bucket(const int* __restrict__ ei,
                         const float* __restrict__ w) {
    int e = blockIdx.x * blockDim.x + threadIdx.x;
    if (e >= NE) return;
    int s = ei[e];
    int d = ei[NE + e];
    int pos = g_rowstart[d] + atomicAdd(&g_cur[d], 1);
    g_esrc[pos]  = s;
    g_enorm[pos] = g_deg[s] * w[e] * g_deg[d];
}

// ---------------- SGEMM: g_h = X @ W  (f32x2 packed FMA) ----------------
// BM=128 rows, BK=32, 256 threads, per-thread 8 rows x DOUT/16 cols
// cols organized as NCH chunks of float4 at (ch*64 + tc*4)
template <int DOUT, int XSEL>
__global__ void __launch_bounds__(256, 2) k_gemm(const float* __restrict__ Xext,
                                                 const float* __restrict__ W) {
    constexpr int BM = 128, BK = 32, TM = 8;
    constexpr int NCH = DOUT / 64;              // 2 for 128, 1 for 64
    __shared__ float Xs[BK][BM + 1];            // pad -> conflict-free transpose store
    __shared__ float Ws[BK][DOUT];

    const float* X = (XSEL < 0) ? Xext : buf<(XSEL < 0) ? 0 : XSEL>();
    float* H = g_h;

    const int tid  = threadIdx.x;
    const int row0 = blockIdx.x * BM;
    const int tr   = tid >> 4;    // 0..15 (8 rows each)
    const int tc   = tid & 15;    // 0..15 (float4 col group per chunk)

    uint64_t acc[TM][NCH * 2];
#pragma unroll
    for (int a = 0; a < TM; a++)
#pragma unroll
        for (int c = 0; c < NCH * 2; c++) acc[a][c] = 0ull;

    for (int k0 = 0; k0 < DIN; k0 += BK) {
        // X tile: float4 global loads, scalar transpose stores (pad -> no conflicts)
#pragma unroll
        for (int j = 0; j < 4; j++) {
            int i4 = tid + j * 256;      // 0..1023
            int m  = i4 >> 3;            // row in tile
            int k4 = i4 & 7;             // float4 index along k
            int r  = row0 + m;
            float4 v = make_float4(0.f, 0.f, 0.f, 0.f);
            if (r < NN)
                v = *reinterpret_cast<const float4*>(&X[(size_t)r * DIN + k0 + k4 * 4]);
            Xs[k4 * 4 + 0][m] = v.x;
            Xs[k4 * 4 + 1][m] = v.y;
            Xs[k4 * 4 + 2][m] = v.z;
            Xs[k4 * 4 + 3][m] = v.w;
        }
        // W tile: float4 loads + stores
#pragma unroll
        for (int i4 = tid; i4 < BK * DOUT / 4; i4 += 256) {
            int k  = i4 / (DOUT / 4);
            int c4 = i4 % (DOUT / 4);
            *reinterpret_cast<float4*>(&Ws[k][c4 * 4]) =
                *reinterpret_cast<const float4*>(&W[(size_t)(k0 + k) * DOUT + c4 * 4]);
        }
        __syncthreads();

#pragma unroll
        for (int k = 0; k < BK; k++) {
            uint64_t xv2[TM];
#pragma unroll
            for (int a = 0; a < TM; a++) {
                float xv = Xs[k][tr * TM + a];
                xv2[a] = pack2(xv, xv);
            }
#pragma unroll
            for (int ch = 0; ch < NCH; ch++) {
                ulonglong2 w01 = *reinterpret_cast<const ulonglong2*>(
                    &Ws[k][ch * 64 + tc * 4]);
#pragma unroll
                for (int a = 0; a < TM; a++) {
                    ffma2(acc[a][ch * 2 + 0], xv2[a], w01.x);
                    ffma2(acc[a][ch * 2 + 1], xv2[a], w01.y);
                }
            }
        }
        __syncthreads();
    }

    // epilogue: float4 stores
#pragma unroll
    for (int a = 0; a < TM; a++) {
        int r = row0 + tr * TM + a;
        if (r >= NN) continue;
#pragma unroll
        for (int ch = 0; ch < NCH; ch++) {
            float4 o;
            unpack2(acc[a][ch * 2 + 0], o.x, o.y);
            unpack2(acc[a][ch * 2 + 1], o.z, o.w);
            *reinterpret_cast<float4*>(&H[(size_t)r * DOUT + ch * 64 + tc * 4]) = o;
        }
    }
}

// ------- fused aggregate: OUT[n] = sum_{CSR[n]} norm*g_h[src] + dinv^2*g_h[n] + bias, relu ----
// one warp per node; 2-way edge unroll for MLP=2
template <int DOUT, bool RELU, int OSEL>
__global__ void k_agg(const float* __restrict__ bias,
                      float* __restrict__ OUText) {
    int warp = (blockIdx.x * blockDim.x + threadIdx.x) >> 5;
    int lane = threadIdx.x & 31;
    if (warp >= NN) return;

    float* OUT = (OSEL < 0) ? OUText : buf<(OSEL < 0) ? 0 : OSEL>();
    const float* H = g_h;

    int beg = g_rowstart[warp];
    int end = g_rowstart[warp + 1];
    float din = g_deg[warp];
    float sn  = din * din;

    if (DOUT == 128) {
        const float4* H4 = reinterpret_cast<const float4*>(H);
        float4 h = H4[(size_t)warp * 32 + lane];
        float4 acc = make_float4(h.x * sn, h.y * sn, h.z * sn, h.w * sn);
        int e = beg;
        for (; e + 1 < end; e += 2) {
            int   s0 = g_esrc[e],     s1 = g_esrc[e + 1];
            float w0 = g_enorm[e],    w1 = g_enorm[e + 1];
            float4 v0 = H4[(size_t)s0 * 32 + lane];
            float4 v1 = H4[(size_t)s1 * 32 + lane];
            acc.x += w0 * v0.x + w1 * v1.x;
            acc.y += w0 * v0.y + w1 * v1.y;
            acc.z += w0 * v0.z + w1 * v1.z;
            acc.w += w0 * v0.w + w1 * v1.w;
        }
        if (e < end) {
            int   s = g_esrc[e];
            float w = g_enorm[e];
            float4 v = H4[(size_t)s * 32 + lane];
            acc.x += w * v.x; acc.y += w * v.y;
            acc.z += w * v.z; acc.w += w * v.w;
        }
        float4 bb = reinterpret_cast<const float4*>(bias)[lane];
        acc.x += bb.x; acc.y += bb.y; acc.z += bb.z; acc.w += bb.w;
        if (RELU) {
            acc.x = fmaxf(acc.x, 0.f); acc.y = fmaxf(acc.y, 0.f);
            acc.z = fmaxf(acc.z, 0.f); acc.w = fmaxf(acc.w, 0.f);
        }
        reinterpret_cast<float4*>(OUT)[(size_t)warp * 32 + lane] = acc;
    } else {
        const float2* H2 = reinterpret_cast<const float2*>(H);
        float2 h = H2[(size_t)warp * 32 + lane];
        float2 acc = make_float2(h.x * sn, h.y * sn);
        int e = beg;
        for (; e + 1 < end; e += 2) {
            int   s0 = g_esrc[e],     s1 = g_esrc[e + 1];
            float w0 = g_enorm[e],    w1 = g_enorm[e + 1];
            float2 v0 = H2[(size_t)s0 * 32 + lane];
            float2 v1 = H2[(size_t)s1 * 32 + lane];
            acc.x += w0 * v0.x + w1 * v1.x;
            acc.y += w0 * v0.y + w1 * v1.y;
        }
        if (e < end) {
            int   s = g_esrc[e];
            float w = g_enorm[e];
            float2 v = H2[(size_t)s * 32 + lane];
            acc.x += w * v.x; acc.y += w * v.y;
        }
        float2 bb = reinterpret_cast<const float2*>(bias)[lane];
        acc.x += bb.x; acc.y += bb.y;
        if (RELU) { acc.x = fmaxf(acc.x, 0.f); acc.y = fmaxf(acc.y, 0.f); }
        reinterpret_cast<float2*>(OUT)[(size_t)warp * 32 + lane] = acc;
    }
}

// ---------------- driver (launches only) ----------------
extern "C" void kernel_launch(void* const* d_in, const int* in_sizes, int n_in,
                              void* d_out, int out_size) {
    const float* x  = (const float*)d_in[0];
    const int*   ei = (const int*)d_in[1];
    const float* ew = (const float*)d_in[2];
    const float* W0 = (const float*)d_in[3];
    const float* b0 = (const float*)d_in[4];
    const float* W1 = (const float*)d_in[5];
    const float* b1 = (const float*)d_in[6];
    const float* W2 = (const float*)d_in[7];
    const float* b2 = (const float*)d_in[8];
    float*       out = (float*)d_out;

    const int T = 256;
    k_init<<<(NN + T - 1) / T, T>>>();
    k_deg_acc<<<(NE + T - 1) / T, T>>>(ei, ew);
    k_scan_a<<<NBLK, 256>>>();
    k_scan_b<<<1, 128>>>();
    k_scan_c<<<NBLK, 256>>>();
    k_bucket<<<(NE + T - 1) / T, T>>>(ei, ew);

    const int gemm_blocks = (NN + 127) / 128;
    const int agg_blocks  = (NN * 32 + T - 1) / T;

    // layer 0: x -> g_a (d=128, relu)
    k_gemm<128, -1><<<gemm_blocks, 256>>>(x, W0);
    k_agg<128, true, 1><<<agg_blocks, T>>>(b0, nullptr);

    // layer 1: g_a -> g_b (d=128, relu)
    k_gemm<128, 1><<<gemm_blocks, 256>>>(nullptr, W1);
    k_agg<128, true, 2><<<agg_blocks, T>>>(b1, nullptr);

    // layer 2: g_b -> out (d=64, no relu)
    k_gemm<64, 2><<<gemm_blocks, 256>>>(nullptr, W2);
    k_agg<64, false, -1><<<agg_blocks, T>>>(b2, out);
}